// round 11
// baseline (speedup 1.0000x reference)
#include <cuda_runtime.h>
#include <cuda_fp16.h>
#include <cstdint>

// ===== problem constants =====
#define E_   8
#define B_   16384
#define DS_  32
#define DA_  8
#define DIN_ 40
#define HID_ 128
#define TM_  128     // batch rows per CTA
#define NTH_ 128     // 4 warps x 32 rows (2 m16 rowtiles per warp)

// ===== SMEM: fragment-linear weights; k16 block (kc,nt) = 512 B, lane = 16 B =====
#define SM_W0   0                        // 2 kc * 16 nt * 512  = 16384   (states part, k 0..31)
#define SM_W0A  16384                    // 16 nt * 32 lane * 8 = 4096    (actions part, k8)
#define SM_W1   20480                    // 8 kc * 16 nt * 512  = 65536
#define SM_W2   86016                    // 8 kc *  4 nt * 512  = 16384
#define SM_BI   102400                   // b0(512) b1(512) b2(128)
#define SM_STAT 103552                   // 64 slots x 128 thr x 4B = 32768
#define SM_TOTAL (SM_STAT + 32768)       // 136320 bytes

// ===== helpers =====
__device__ __forceinline__ uint32_t packh2(float lo, float hi) {
    uint32_t d;
    asm("cvt.rn.f16x2.f32 %0, %1, %2;" : "=r"(d) : "f"(hi), "f"(lo));
    return d;
}
__device__ __forceinline__ float h2f_lo(uint32_t u) {
    return __half2float(__ushort_as_half((unsigned short)(u & 0xFFFFu)));
}
__device__ __forceinline__ float h2f_hi(uint32_t u) {
    return __half2float(__ushort_as_half((unsigned short)(u >> 16)));
}

__device__ __forceinline__ void mma16816(float d[4], const uint32_t a[4],
                                         uint32_t b0, uint32_t b1) {
    asm volatile(
        "mma.sync.aligned.m16n8k16.row.col.f32.f16.f16.f32 "
        "{%0,%1,%2,%3}, {%4,%5,%6,%7}, {%8,%9}, {%0,%1,%2,%3};"
        : "+f"(d[0]), "+f"(d[1]), "+f"(d[2]), "+f"(d[3])
        : "r"(a[0]), "r"(a[1]), "r"(a[2]), "r"(a[3]), "r"(b0), "r"(b1));
}
__device__ __forceinline__ void mma1688(float d[4], uint32_t a0, uint32_t a1,
                                        uint32_t b0) {
    asm volatile(
        "mma.sync.aligned.m16n8k8.row.col.f32.f16.f16.f32 "
        "{%0,%1,%2,%3}, {%4,%5}, {%6}, {%0,%1,%2,%3};"
        : "+f"(d[0]), "+f"(d[1]), "+f"(d[2]), "+f"(d[3])
        : "r"(a0), "r"(a1), "r"(b0));
}

// bias + leaky + fp16 pack of one accumulator ntile
__device__ __forceinline__ void cvt_act(const float acc[4], float2 bb,
                                        uint32_t& h01, uint32_t& h23) {
    float v0 = acc[0] + bb.x, v1 = acc[1] + bb.y;
    float v2 = acc[2] + bb.x, v3 = acc[3] + bb.y;
    v0 = fmaxf(v0, 0.01f * v0); v1 = fmaxf(v1, 0.01f * v1);
    v2 = fmaxf(v2, 0.01f * v2); v3 = fmaxf(v3, 0.01f * v3);
    h01 = packh2(v0, v1);
    h23 = packh2(v2, v3);
}

// stage one weight matrix [Kreal][N] row-major into fragment-linear hi/lo fp16 SMEM (k16 blocks)
__device__ void stage_w(const float* __restrict__ g, int KC, int NT,
                        int N, char* dst) {
    const int total = KC * NT * 32;
    for (int idx = threadIdx.x; idx < total; idx += NTH_) {
        int lane = idx & 31;
        int blk  = idx >> 5;
        int qk = lane & 3, rr = lane >> 2;
        int nt = blk % NT, kc = blk / NT;
        int n  = nt * 8 + rr;
        int k0 = kc * 16 + qk * 2;
        float f0 = g[(size_t)k0 * N + n];
        float f1 = g[(size_t)(k0 + 1) * N + n];
        float f2 = g[(size_t)(k0 + 8) * N + n];
        float f3 = g[(size_t)(k0 + 9) * N + n];
        uint32_t h01 = packh2(f0, f1);
        uint32_t h23 = packh2(f2, f3);
        uint32_t l01 = packh2(f0 - h2f_lo(h01), f1 - h2f_hi(h01));
        uint32_t l23 = packh2(f2 - h2f_lo(h23), f3 - h2f_hi(h23));
        *(uint4*)(dst + (size_t)blk * 512 + lane * 16) = make_uint4(h01, h23, l01, l23);
    }
}

__global__ __launch_bounds__(NTH_, 1)
void ensemble_mlp_mma(const float* __restrict__ states,
                      const float* __restrict__ actions,
                      const float* __restrict__ W0, const float* __restrict__ b0,
                      const float* __restrict__ W1, const float* __restrict__ b1,
                      const float* __restrict__ W2, const float* __restrict__ b2,
                      float* __restrict__ out)
{
    extern __shared__ char smc[];
    float* sb0 = (float*)(smc + SM_BI);
    float* sb1 = sb0 + 128;
    float* sb2 = sb1 + 128;
    float* sstat = (float*)(smc + SM_STAT);  // [64 slots][NTH_]: 0..31 sums, 32..63 sqs

    const int tid  = threadIdx.x;
    const int wid  = tid >> 5;
    const int lane = tid & 31;
    const int qk   = lane & 3;     // k-quad within fragment
    const int rr   = lane >> 2;    // row (and B-col) within fragment
    const int j     = blockIdx.y;
    const int btile = blockIdx.x * TM_;

    // ---- stage weights (hi/lo fp16) + biases; zero stats ----
    stage_w(W0 + (size_t)j * DIN_ * HID_, 2, 16, HID_, smc + SM_W0);  // k 0..31 (states)
    {   // actions part of W0 (k 32..39) as k8 fragments: uint2 {h01, l01}
        const float* g = W0 + (size_t)j * DIN_ * HID_;
        for (int idx = tid; idx < 16 * 32; idx += NTH_) {
            int lane2 = idx & 31;
            int nt = idx >> 5;
            int q = lane2 & 3, r2 = lane2 >> 2;
            int n = nt * 8 + r2;
            int k0 = 32 + q * 2;
            float f0 = g[(size_t)k0 * HID_ + n];
            float f1 = g[(size_t)(k0 + 1) * HID_ + n];
            uint32_t h01 = packh2(f0, f1);
            uint32_t l01 = packh2(f0 - h2f_lo(h01), f1 - h2f_hi(h01));
            *(uint2*)(smc + SM_W0A + (size_t)idx * 8) = make_uint2(h01, l01);
        }
    }
    stage_w(W1 + (size_t)j * HID_ * HID_, 8, 16, HID_, smc + SM_W1);
    stage_w(W2 + (size_t)j * HID_ * DS_,  8,  4, DS_,  smc + SM_W2);
    if (tid < HID_) { sb0[tid] = b0[j * HID_ + tid]; sb1[tid] = b1[j * HID_ + tid]; }
    if (tid < DS_)  { sb2[tid] = b2[j * DS_ + tid]; }
    #pragma unroll
    for (int s = 0; s < 64; ++s) sstat[s * NTH_ + tid] = 0.f;
    __syncthreads();   // the ONLY barrier — i-loop below is barrier-free

    // per-lane fragment base pointers
    const char* w0b  = smc + SM_W0  + lane * 16;
    const char* w0ab = smc + SM_W0A + lane * 8;
    const char* w1b  = smc + SM_W1  + lane * 16;
    const char* w2b  = smc + SM_W2  + lane * 16;
    float* st = sstat + tid;

    // per-rowtile gmem activation pointers (rowtile rt covers rows wid*32+rt*16 + {rr, rr+8})
    const int rbase0 = btile + wid * 32 + rr;          // rt 0
    const int rbase1 = rbase0 + 16;                    // rt 1
    const float* srow[2] = { states  + (size_t)rbase0 * DS_ + qk * 2,
                             states  + (size_t)rbase1 * DS_ + qk * 2 };
    const float* arow[2] = { actions + (size_t)rbase0 * DA_ + qk * 2,
                             actions + (size_t)rbase1 * DA_ + qk * 2 };

    uint32_t aH[2][32], aB[2][32];   // activations: layer0->1 and layer1->2

    for (int i = 0; i < E_; ++i) {
        // ================= layer 0: K=40 (2x k16 + 1x k8), N=128, full-N =========
        {
            float acc[2][16][4];
            #pragma unroll
            for (int rt = 0; rt < 2; ++rt)
                #pragma unroll
                for (int nt = 0; nt < 16; ++nt)
                    #pragma unroll
                    for (int t = 0; t < 4; ++t) acc[rt][nt][t] = 0.f;

            uint32_t xr[2][2][4], xa[2][2];
            #pragma unroll
            for (int rt = 0; rt < 2; ++rt) {
                #pragma unroll
                for (int kc = 0; kc < 2; ++kc) {
                    float2 x00 = __ldg((const float2*)(srow[rt] + kc * 16));
                    float2 x01 = __ldg((const float2*)(srow[rt] + kc * 16 + 8 * DS_));
                    float2 x10 = __ldg((const float2*)(srow[rt] + kc * 16 + 8));
                    float2 x11 = __ldg((const float2*)(srow[rt] + kc * 16 + 8 + 8 * DS_));
                    xr[rt][kc][0] = packh2(x00.x, x00.y);
                    xr[rt][kc][1] = packh2(x01.x, x01.y);
                    xr[rt][kc][2] = packh2(x10.x, x10.y);
                    xr[rt][kc][3] = packh2(x11.x, x11.y);
                }
                float2 a0 = __ldg((const float2*)(arow[rt]));
                float2 a1 = __ldg((const float2*)(arow[rt] + 8 * DA_));
                xa[rt][0] = packh2(a0.x, a0.y);
                xa[rt][1] = packh2(a1.x, a1.y);
            }
            #pragma unroll
            for (int kc = 0; kc < 2; ++kc)
                #pragma unroll
                for (int nt = 0; nt < 16; ++nt) {
                    uint4 bv = *(const uint4*)(w0b + (kc * 16 + nt) * 512);
                    #pragma unroll
                    for (int rt = 0; rt < 2; ++rt) {
                        mma16816(acc[rt][nt], xr[rt][kc], bv.x, bv.y);
                        mma16816(acc[rt][nt], xr[rt][kc], bv.z, bv.w);
                    }
                }
            #pragma unroll
            for (int nt = 0; nt < 16; ++nt) {
                uint2 bv = *(const uint2*)(w0ab + nt * 256);
                #pragma unroll
                for (int rt = 0; rt < 2; ++rt) {
                    mma1688(acc[rt][nt], xa[rt][0], xa[rt][1], bv.x);
                    mma1688(acc[rt][nt], xa[rt][0], xa[rt][1], bv.y);
                }
            }
            #pragma unroll
            for (int nt = 0; nt < 16; ++nt) {
                float2 bb = *(const float2*)(sb0 + nt * 8 + qk * 2);
                #pragma unroll
                for (int rt = 0; rt < 2; ++rt)
                    cvt_act(acc[rt][nt], bb, aH[rt][2*nt], aH[rt][2*nt+1]);
            }
        }

        // ================= layer 1: K=128, N=128 in two N=64 halves =============
        #pragma unroll
        for (int nh = 0; nh < 2; ++nh) {
            float acc[2][8][4];
            #pragma unroll
            for (int rt = 0; rt < 2; ++rt)
                #pragma unroll
                for (int nt = 0; nt < 8; ++nt)
                    #pragma unroll
                    for (int t = 0; t < 4; ++t) acc[rt][nt][t] = 0.f;

            #pragma unroll
            for (int kc = 0; kc < 8; ++kc)
                #pragma unroll
                for (int nt = 0; nt < 8; ++nt) {
                    uint4 bv = *(const uint4*)(w1b + (kc * 16 + nh * 8 + nt) * 512);
                    #pragma unroll
                    for (int rt = 0; rt < 2; ++rt) {
                        mma16816(acc[rt][nt], aH[rt] + 4 * kc, bv.x, bv.y);
                        mma16816(acc[rt][nt], aH[rt] + 4 * kc, bv.z, bv.w);
                    }
                }
            #pragma unroll
            for (int nt = 0; nt < 8; ++nt) {
                float2 bb = *(const float2*)(sb1 + (nh * 8 + nt) * 8 + qk * 2);
                #pragma unroll
                for (int rt = 0; rt < 2; ++rt)
                    cvt_act(acc[rt][nt], bb, aB[rt][nh*16 + 2*nt], aB[rt][nh*16 + 2*nt+1]);
            }
        }

        // ================= layer 2: K=128, N=32; stats into SMEM =================
        {
            float acc[2][4][4];
            #pragma unroll
            for (int rt = 0; rt < 2; ++rt)
                #pragma unroll
                for (int nt = 0; nt < 4; ++nt)
                    #pragma unroll
                    for (int t = 0; t < 4; ++t) acc[rt][nt][t] = 0.f;

            #pragma unroll
            for (int kc = 0; kc < 8; ++kc)
                #pragma unroll
                for (int nt = 0; nt < 4; ++nt) {
                    uint4 bv = *(const uint4*)(w2b + (kc * 4 + nt) * 512);
                    #pragma unroll
                    for (int rt = 0; rt < 2; ++rt) {
                        mma16816(acc[rt][nt], aB[rt] + 4 * kc, bv.x, bv.y);
                        mma16816(acc[rt][nt], aB[rt] + 4 * kc, bv.z, bv.w);
                    }
                }
            #pragma unroll
            for (int rt = 0; rt < 2; ++rt)
                #pragma unroll
                for (int nt = 0; nt < 4; ++nt) {
                    float2 bb = *(const float2*)(sb2 + nt * 8 + qk * 2);
                    #pragma unroll
                    for (int t = 0; t < 4; ++t) {
                        float p = acc[rt][nt][t] + ((t & 1) ? bb.y : bb.x);
                        const int slot = rt * 16 + nt * 4 + t;
                        st[slot * NTH_]        += p;
                        st[(32 + slot) * NTH_]  = fmaf(p, p, st[(32 + slot) * NTH_]);
                    }
                }
        }

        #pragma unroll
        for (int rt = 0; rt < 2; ++rt) {
            srow[rt] += (size_t)B_ * DS_;
            arow[rt] += (size_t)B_ * DA_;
        }
    }

    // ---- epilogue: mean/var over the 8 members; outputs ----
    const size_t var_off = (size_t)E_ * B_ * DS_;
    #pragma unroll
    for (int rt = 0; rt < 2; ++rt) {
        const size_t row_lo = (size_t)j * B_ + btile + wid * 32 + rt * 16 + rr;
        const size_t row_hi = row_lo + 8;
        #pragma unroll
        for (int nt = 0; nt < 4; ++nt) {
            const int c0 = nt * 8 + qk * 2;
            const int sbase = rt * 16 + nt * 4;
            {
                const size_t o = row_lo * DS_ + c0;
                float2 stv = __ldg((const float2*)(states + o));
                float s0 = st[(sbase+0) * NTH_], s1 = st[(sbase+1) * NTH_];
                float q0 = st[(32+sbase+0) * NTH_], q1 = st[(32+sbase+1) * NTH_];
                float m0 = s0 * 0.125f, m1 = s1 * 0.125f;
                float v0 = (q0 - 8.f * m0 * m0) * (1.f / 7.f);
                float v1 = (q1 - 8.f * m1 * m1) * (1.f / 7.f);
                *(float2*)(out + o)           = make_float2(m0 + stv.x, m1 + stv.y);
                *(float2*)(out + var_off + o) = make_float2(v0, v1);
            }
            {
                const size_t o = row_hi * DS_ + c0;
                float2 stv = __ldg((const float2*)(states + o));
                float s2 = st[(sbase+2) * NTH_], s3 = st[(sbase+3) * NTH_];
                float q2 = st[(32+sbase+2) * NTH_], q3 = st[(32+sbase+3) * NTH_];
                float m2 = s2 * 0.125f, m3 = s3 * 0.125f;
                float v2 = (q2 - 8.f * m2 * m2) * (1.f / 7.f);
                float v3 = (q3 - 8.f * m3 * m3) * (1.f / 7.f);
                *(float2*)(out + o)           = make_float2(m2 + stv.x, m3 + stv.y);
                *(float2*)(out + var_off + o) = make_float2(v2, v3);
            }
        }
    }
}

extern "C" void kernel_launch(void* const* d_in, const int* in_sizes, int n_in,
                              void* d_out, int out_size)
{
    const float* states  = (const float*)d_in[0];
    const float* actions = (const float*)d_in[1];
    const float* W0      = (const float*)d_in[2];
    const float* b0      = (const float*)d_in[3];
    const float* W1      = (const float*)d_in[4];
    const float* b1      = (const float*)d_in[5];
    const float* W2      = (const float*)d_in[6];
    const float* b2      = (const float*)d_in[7];
    float* out = (float*)d_out;

    cudaFuncSetAttribute(ensemble_mlp_mma,
                         cudaFuncAttributeMaxDynamicSharedMemorySize, SM_TOTAL);

    dim3 grid(B_ / TM_, E_);   // 128 x 8 = 1024 CTAs
    ensemble_mlp_mma<<<grid, NTH_, SM_TOTAL>>>(states, actions,
                                               W0, b0, W1, b1, W2, b2, out);
}

// round 12
// speedup vs baseline: 1.0751x; 1.0751x over previous
#include <cuda_runtime.h>
#include <cuda_fp16.h>
#include <cstdint>

// ===== problem constants =====
#define E_   8
#define B_   16384
#define DS_  32
#define DA_  8
#define DIN_ 40
#define HID_ 128
#define TM_  256     // batch rows per CTA (8 warps x 32 rows)
#define NTH_ 256     // 8 warps, 2 per SMSP

// ===== SMEM: fragment-linear weights; k16 block (kc,nt) = 512 B, lane = 16 B =====
#define SM_W0   0                        // 2 kc * 16 nt * 512  = 16384   (states part, k 0..31)
#define SM_W0A  16384                    // 16 nt * 32 lane * 8 = 4096    (actions part, k8)
#define SM_W1   20480                    // 8 kc * 16 nt * 512  = 65536
#define SM_W2   86016                    // 8 kc *  4 nt * 512  = 16384
#define SM_BI   102400                   // b0(512) b1(512) b2(128)
#define SM_STAT 103552                   // 64 slots x 256 thr x 4B = 65536
#define SM_TOTAL (SM_STAT + 65536)       // 169088 bytes

// ===== helpers =====
__device__ __forceinline__ uint32_t packh2(float lo, float hi) {
    uint32_t d;
    asm("cvt.rn.f16x2.f32 %0, %1, %2;" : "=r"(d) : "f"(hi), "f"(lo));
    return d;
}
__device__ __forceinline__ float h2f_lo(uint32_t u) {
    return __half2float(__ushort_as_half((unsigned short)(u & 0xFFFFu)));
}
__device__ __forceinline__ float h2f_hi(uint32_t u) {
    return __half2float(__ushort_as_half((unsigned short)(u >> 16)));
}

__device__ __forceinline__ void mma16816(float d[4], const uint32_t a[4],
                                         uint32_t b0, uint32_t b1) {
    asm volatile(
        "mma.sync.aligned.m16n8k16.row.col.f32.f16.f16.f32 "
        "{%0,%1,%2,%3}, {%4,%5,%6,%7}, {%8,%9}, {%0,%1,%2,%3};"
        : "+f"(d[0]), "+f"(d[1]), "+f"(d[2]), "+f"(d[3])
        : "r"(a[0]), "r"(a[1]), "r"(a[2]), "r"(a[3]), "r"(b0), "r"(b1));
}
__device__ __forceinline__ void mma1688(float d[4], uint32_t a0, uint32_t a1,
                                        uint32_t b0) {
    asm volatile(
        "mma.sync.aligned.m16n8k8.row.col.f32.f16.f16.f32 "
        "{%0,%1,%2,%3}, {%4,%5}, {%6}, {%0,%1,%2,%3};"
        : "+f"(d[0]), "+f"(d[1]), "+f"(d[2]), "+f"(d[3])
        : "r"(a0), "r"(a1), "r"(b0));
}

// bias + leaky + fp16 pack of one accumulator ntile
__device__ __forceinline__ void cvt_act(const float acc[4], float2 bb,
                                        uint32_t& h01, uint32_t& h23) {
    float v0 = acc[0] + bb.x, v1 = acc[1] + bb.y;
    float v2 = acc[2] + bb.x, v3 = acc[3] + bb.y;
    v0 = fmaxf(v0, 0.01f * v0); v1 = fmaxf(v1, 0.01f * v1);
    v2 = fmaxf(v2, 0.01f * v2); v3 = fmaxf(v3, 0.01f * v3);
    h01 = packh2(v0, v1);
    h23 = packh2(v2, v3);
}

// stage one weight matrix [Kreal][N] row-major into fragment-linear hi/lo fp16 SMEM (k16 blocks)
__device__ void stage_w(const float* __restrict__ g, int KC, int NT,
                        int N, char* dst) {
    const int total = KC * NT * 32;
    for (int idx = threadIdx.x; idx < total; idx += NTH_) {
        int lane = idx & 31;
        int blk  = idx >> 5;
        int qk = lane & 3, rr = lane >> 2;
        int nt = blk % NT, kc = blk / NT;
        int n  = nt * 8 + rr;
        int k0 = kc * 16 + qk * 2;
        float f0 = g[(size_t)k0 * N + n];
        float f1 = g[(size_t)(k0 + 1) * N + n];
        float f2 = g[(size_t)(k0 + 8) * N + n];
        float f3 = g[(size_t)(k0 + 9) * N + n];
        uint32_t h01 = packh2(f0, f1);
        uint32_t h23 = packh2(f2, f3);
        uint32_t l01 = packh2(f0 - h2f_lo(h01), f1 - h2f_hi(h01));
        uint32_t l23 = packh2(f2 - h2f_lo(h23), f3 - h2f_hi(h23));
        *(uint4*)(dst + (size_t)blk * 512 + lane * 16) = make_uint4(h01, h23, l01, l23);
    }
}

__global__ __launch_bounds__(NTH_, 1)
void ensemble_mlp_mma(const float* __restrict__ states,
                      const float* __restrict__ actions,
                      const float* __restrict__ W0, const float* __restrict__ b0,
                      const float* __restrict__ W1, const float* __restrict__ b1,
                      const float* __restrict__ W2, const float* __restrict__ b2,
                      float* __restrict__ out)
{
    extern __shared__ char smc[];
    float* sb0 = (float*)(smc + SM_BI);
    float* sb1 = sb0 + 128;
    float* sb2 = sb1 + 128;
    float* sstat = (float*)(smc + SM_STAT);  // [64 slots][NTH_]: 0..31 sums, 32..63 sqs

    const int tid  = threadIdx.x;
    const int wid  = tid >> 5;
    const int lane = tid & 31;
    const int qk   = lane & 3;     // k-quad within fragment
    const int rr   = lane >> 2;    // row (and B-col) within fragment
    const int j     = blockIdx.y;
    const int btile = blockIdx.x * TM_;

    // ---- stage weights (hi/lo fp16) + biases; zero stats ----
    stage_w(W0 + (size_t)j * DIN_ * HID_, 2, 16, HID_, smc + SM_W0);  // k 0..31 (states)
    {   // actions part of W0 (k 32..39) as k8 fragments: uint2 {h01, l01}
        const float* g = W0 + (size_t)j * DIN_ * HID_;
        for (int idx = tid; idx < 16 * 32; idx += NTH_) {
            int lane2 = idx & 31;
            int nt = idx >> 5;
            int q = lane2 & 3, r2 = lane2 >> 2;
            int n = nt * 8 + r2;
            int k0 = 32 + q * 2;
            float f0 = g[(size_t)k0 * HID_ + n];
            float f1 = g[(size_t)(k0 + 1) * HID_ + n];
            uint32_t h01 = packh2(f0, f1);
            uint32_t l01 = packh2(f0 - h2f_lo(h01), f1 - h2f_hi(h01));
            *(uint2*)(smc + SM_W0A + (size_t)idx * 8) = make_uint2(h01, l01);
        }
    }
    stage_w(W1 + (size_t)j * HID_ * HID_, 8, 16, HID_, smc + SM_W1);
    stage_w(W2 + (size_t)j * HID_ * DS_,  8,  4, DS_,  smc + SM_W2);
    if (tid < HID_) { sb0[tid] = b0[j * HID_ + tid]; sb1[tid] = b1[j * HID_ + tid]; }
    if (tid < DS_)  { sb2[tid] = b2[j * DS_ + tid]; }
    #pragma unroll
    for (int s = 0; s < 64; ++s) sstat[s * NTH_ + tid] = 0.f;
    __syncthreads();   // the ONLY barrier — i-loop below is barrier-free

    // per-lane fragment base pointers
    const char* w0b  = smc + SM_W0  + lane * 16;
    const char* w0ab = smc + SM_W0A + lane * 8;
    const char* w1b  = smc + SM_W1  + lane * 16;
    const char* w2b  = smc + SM_W2  + lane * 16;
    float* st = sstat + tid;

    // per-rowtile gmem activation pointers (rowtile rt covers rows wid*32+rt*16 + {rr, rr+8})
    const int rbase0 = btile + wid * 32 + rr;          // rt 0
    const int rbase1 = rbase0 + 16;                    // rt 1
    const float* srow[2] = { states  + (size_t)rbase0 * DS_ + qk * 2,
                             states  + (size_t)rbase1 * DS_ + qk * 2 };
    const float* arow[2] = { actions + (size_t)rbase0 * DA_ + qk * 2,
                             actions + (size_t)rbase1 * DA_ + qk * 2 };

    uint32_t aH[2][32], aB[2][32];   // activations: layer0->1 and layer1->2

    for (int i = 0; i < E_; ++i) {
        // ====== layer 0: K=40 (2x k16 + 1x k8), N=128 in two N=64 halves ======
        {
            uint32_t xr[2][2][4], xa[2][2];
            #pragma unroll
            for (int rt = 0; rt < 2; ++rt) {
                #pragma unroll
                for (int kc = 0; kc < 2; ++kc) {
                    float2 x00 = __ldg((const float2*)(srow[rt] + kc * 16));
                    float2 x01 = __ldg((const float2*)(srow[rt] + kc * 16 + 8 * DS_));
                    float2 x10 = __ldg((const float2*)(srow[rt] + kc * 16 + 8));
                    float2 x11 = __ldg((const float2*)(srow[rt] + kc * 16 + 8 + 8 * DS_));
                    xr[rt][kc][0] = packh2(x00.x, x00.y);
                    xr[rt][kc][1] = packh2(x01.x, x01.y);
                    xr[rt][kc][2] = packh2(x10.x, x10.y);
                    xr[rt][kc][3] = packh2(x11.x, x11.y);
                }
                float2 a0 = __ldg((const float2*)(arow[rt]));
                float2 a1 = __ldg((const float2*)(arow[rt] + 8 * DA_));
                xa[rt][0] = packh2(a0.x, a0.y);
                xa[rt][1] = packh2(a1.x, a1.y);
            }
            #pragma unroll
            for (int nh = 0; nh < 2; ++nh) {
                float acc[2][8][4];
                #pragma unroll
                for (int rt = 0; rt < 2; ++rt)
                    #pragma unroll
                    for (int nt = 0; nt < 8; ++nt)
                        #pragma unroll
                        for (int t = 0; t < 4; ++t) acc[rt][nt][t] = 0.f;

                #pragma unroll
                for (int kc = 0; kc < 2; ++kc)
                    #pragma unroll
                    for (int nt = 0; nt < 8; ++nt) {
                        uint4 bv = *(const uint4*)(w0b + (kc * 16 + nh * 8 + nt) * 512);
                        #pragma unroll
                        for (int rt = 0; rt < 2; ++rt) {
                            mma16816(acc[rt][nt], xr[rt][kc], bv.x, bv.y);
                            mma16816(acc[rt][nt], xr[rt][kc], bv.z, bv.w);
                        }
                    }
                #pragma unroll
                for (int nt = 0; nt < 8; ++nt) {
                    uint2 bv = *(const uint2*)(w0ab + (nh * 8 + nt) * 256);
                    #pragma unroll
                    for (int rt = 0; rt < 2; ++rt) {
                        mma1688(acc[rt][nt], xa[rt][0], xa[rt][1], bv.x);
                        mma1688(acc[rt][nt], xa[rt][0], xa[rt][1], bv.y);
                    }
                }
                #pragma unroll
                for (int nt = 0; nt < 8; ++nt) {
                    float2 bb = *(const float2*)(sb0 + (nh * 8 + nt) * 8 + qk * 2);
                    #pragma unroll
                    for (int rt = 0; rt < 2; ++rt)
                        cvt_act(acc[rt][nt], bb, aH[rt][nh*16 + 2*nt], aH[rt][nh*16 + 2*nt+1]);
                }
            }
        }

        // ================= layer 1: K=128, N=128 in two N=64 halves =============
        #pragma unroll
        for (int nh = 0; nh < 2; ++nh) {
            float acc[2][8][4];
            #pragma unroll
            for (int rt = 0; rt < 2; ++rt)
                #pragma unroll
                for (int nt = 0; nt < 8; ++nt)
                    #pragma unroll
                    for (int t = 0; t < 4; ++t) acc[rt][nt][t] = 0.f;

            #pragma unroll
            for (int kc = 0; kc < 8; ++kc)
                #pragma unroll
                for (int nt = 0; nt < 8; ++nt) {
                    uint4 bv = *(const uint4*)(w1b + (kc * 16 + nh * 8 + nt) * 512);
                    #pragma unroll
                    for (int rt = 0; rt < 2; ++rt) {
                        mma16816(acc[rt][nt], aH[rt] + 4 * kc, bv.x, bv.y);
                        mma16816(acc[rt][nt], aH[rt] + 4 * kc, bv.z, bv.w);
                    }
                }
            #pragma unroll
            for (int nt = 0; nt < 8; ++nt) {
                float2 bb = *(const float2*)(sb1 + (nh * 8 + nt) * 8 + qk * 2);
                #pragma unroll
                for (int rt = 0; rt < 2; ++rt)
                    cvt_act(acc[rt][nt], bb, aB[rt][nh*16 + 2*nt], aB[rt][nh*16 + 2*nt+1]);
            }
        }

        // ================= layer 2: K=128, N=32; stats into SMEM =================
        {
            float acc[2][4][4];
            #pragma unroll
            for (int rt = 0; rt < 2; ++rt)
                #pragma unroll
                for (int nt = 0; nt < 4; ++nt)
                    #pragma unroll
                    for (int t = 0; t < 4; ++t) acc[rt][nt][t] = 0.f;

            #pragma unroll
            for (int kc = 0; kc < 8; ++kc)
                #pragma unroll
                for (int nt = 0; nt < 4; ++nt) {
                    uint4 bv = *(const uint4*)(w2b + (kc * 4 + nt) * 512);
                    #pragma unroll
                    for (int rt = 0; rt < 2; ++rt) {
                        mma16816(acc[rt][nt], aB[rt] + 4 * kc, bv.x, bv.y);
                        mma16816(acc[rt][nt], aB[rt] + 4 * kc, bv.z, bv.w);
                    }
                }
            #pragma unroll
            for (int rt = 0; rt < 2; ++rt)
                #pragma unroll
                for (int nt = 0; nt < 4; ++nt) {
                    float2 bb = *(const float2*)(sb2 + nt * 8 + qk * 2);
                    #pragma unroll
                    for (int t = 0; t < 4; ++t) {
                        float p = acc[rt][nt][t] + ((t & 1) ? bb.y : bb.x);
                        const int slot = rt * 16 + nt * 4 + t;
                        st[slot * NTH_]        += p;
                        st[(32 + slot) * NTH_]  = fmaf(p, p, st[(32 + slot) * NTH_]);
                    }
                }
        }

        #pragma unroll
        for (int rt = 0; rt < 2; ++rt) {
            srow[rt] += (size_t)B_ * DS_;
            arow[rt] += (size_t)B_ * DA_;
        }
    }

    // ---- epilogue: mean/var over the 8 members; outputs ----
    const size_t var_off = (size_t)E_ * B_ * DS_;
    #pragma unroll
    for (int rt = 0; rt < 2; ++rt) {
        const size_t row_lo = (size_t)j * B_ + btile + wid * 32 + rt * 16 + rr;
        const size_t row_hi = row_lo + 8;
        #pragma unroll
        for (int nt = 0; nt < 4; ++nt) {
            const int c0 = nt * 8 + qk * 2;
            const int sbase = rt * 16 + nt * 4;
            {
                const size_t o = row_lo * DS_ + c0;
                float2 stv = __ldg((const float2*)(states + o));
                float s0 = st[(sbase+0) * NTH_], s1 = st[(sbase+1) * NTH_];
                float q0 = st[(32+sbase+0) * NTH_], q1 = st[(32+sbase+1) * NTH_];
                float m0 = s0 * 0.125f, m1 = s1 * 0.125f;
                float v0 = (q0 - 8.f * m0 * m0) * (1.f / 7.f);
                float v1 = (q1 - 8.f * m1 * m1) * (1.f / 7.f);
                *(float2*)(out + o)           = make_float2(m0 + stv.x, m1 + stv.y);
                *(float2*)(out + var_off + o) = make_float2(v0, v1);
            }
            {
                const size_t o = row_hi * DS_ + c0;
                float2 stv = __ldg((const float2*)(states + o));
                float s2 = st[(sbase+2) * NTH_], s3 = st[(sbase+3) * NTH_];
                float q2 = st[(32+sbase+2) * NTH_], q3 = st[(32+sbase+3) * NTH_];
                float m2 = s2 * 0.125f, m3 = s3 * 0.125f;
                float v2 = (q2 - 8.f * m2 * m2) * (1.f / 7.f);
                float v3 = (q3 - 8.f * m3 * m3) * (1.f / 7.f);
                *(float2*)(out + o)           = make_float2(m2 + stv.x, m3 + stv.y);
                *(float2*)(out + var_off + o) = make_float2(v2, v3);
            }
        }
    }
}

extern "C" void kernel_launch(void* const* d_in, const int* in_sizes, int n_in,
                              void* d_out, int out_size)
{
    const float* states  = (const float*)d_in[0];
    const float* actions = (const float*)d_in[1];
    const float* W0      = (const float*)d_in[2];
    const float* b0      = (const float*)d_in[3];
    const float* W1      = (const float*)d_in[4];
    const float* b1      = (const float*)d_in[5];
    const float* W2      = (const float*)d_in[6];
    const float* b2      = (const float*)d_in[7];
    float* out = (float*)d_out;

    cudaFuncSetAttribute(ensemble_mlp_mma,
                         cudaFuncAttributeMaxDynamicSharedMemorySize, SM_TOTAL);

    dim3 grid(B_ / TM_, E_);   // 64 x 8 = 512 CTAs
    ensemble_mlp_mma<<<grid, NTH_, SM_TOTAL>>>(states, actions,
                                               W0, b0, W1, b1, W2, b2, out);
}

// round 13
// speedup vs baseline: 1.7091x; 1.5897x over previous
#include <cuda_runtime.h>
#include <cuda_fp16.h>
#include <cstdint>

// ===== problem constants =====
#define E_   8
#define B_   16384
#define DS_  32
#define DA_  8
#define DIN_ 40
#define HID_ 128
#define TM_  128     // batch rows per CTA
#define NTH_ 256     // 8 warps x 16 rows

// ===== SMEM: fragment-linear single-fp16 weights; k16 block (kc,nt) = 256 B, lane = 8 B =====
#define SM_W0   0                        // 2 kc * 16 nt * 256  = 8192    (states part, k 0..31)
#define SM_W0A  8192                     // 16 nt * 32 lane * 4 = 2048    (actions part, k8)
#define SM_W1   10240                    // 8 kc * 16 nt * 256  = 32768
#define SM_W2   43008                    // 8 kc *  4 nt * 256  = 8192
#define SM_BI   51200                    // b0(512) b1(512) b2(128)
#define SM_TOTAL (SM_BI + 1152)          // 52352 bytes

// ===== helpers =====
__device__ __forceinline__ uint32_t packh2(float lo, float hi) {
    uint32_t d;
    asm("cvt.rn.f16x2.f32 %0, %1, %2;" : "=r"(d) : "f"(hi), "f"(lo));
    return d;
}

__device__ __forceinline__ void mma16816(float d[4], const uint32_t a[4],
                                         uint32_t b0, uint32_t b1) {
    asm volatile(
        "mma.sync.aligned.m16n8k16.row.col.f32.f16.f16.f32 "
        "{%0,%1,%2,%3}, {%4,%5,%6,%7}, {%8,%9}, {%0,%1,%2,%3};"
        : "+f"(d[0]), "+f"(d[1]), "+f"(d[2]), "+f"(d[3])
        : "r"(a[0]), "r"(a[1]), "r"(a[2]), "r"(a[3]), "r"(b0), "r"(b1));
}
__device__ __forceinline__ void mma1688(float d[4], uint32_t a0, uint32_t a1,
                                        uint32_t b0) {
    asm volatile(
        "mma.sync.aligned.m16n8k8.row.col.f32.f16.f16.f32 "
        "{%0,%1,%2,%3}, {%4,%5}, {%6}, {%0,%1,%2,%3};"
        : "+f"(d[0]), "+f"(d[1]), "+f"(d[2]), "+f"(d[3])
        : "r"(a0), "r"(a1), "r"(b0));
}

// bias + leaky + fp16 pack of one accumulator ntile
__device__ __forceinline__ void cvt_act(const float acc[4], float2 bb,
                                        uint32_t& h01, uint32_t& h23) {
    float v0 = acc[0] + bb.x, v1 = acc[1] + bb.y;
    float v2 = acc[2] + bb.x, v3 = acc[3] + bb.y;
    v0 = fmaxf(v0, 0.01f * v0); v1 = fmaxf(v1, 0.01f * v1);
    v2 = fmaxf(v2, 0.01f * v2); v3 = fmaxf(v3, 0.01f * v3);
    h01 = packh2(v0, v1);
    h23 = packh2(v2, v3);
}

// stage one weight matrix [Kreal][N] row-major into fragment-linear single-fp16 SMEM
__device__ void stage_w(const float* __restrict__ g, int KC, int NT,
                        int N, char* dst) {
    const int total = KC * NT * 32;
    for (int idx = threadIdx.x; idx < total; idx += NTH_) {
        int lane = idx & 31;
        int blk  = idx >> 5;
        int qk = lane & 3, rr = lane >> 2;
        int nt = blk % NT, kc = blk / NT;
        int n  = nt * 8 + rr;
        int k0 = kc * 16 + qk * 2;
        float f0 = g[(size_t)k0 * N + n];
        float f1 = g[(size_t)(k0 + 1) * N + n];
        float f2 = g[(size_t)(k0 + 8) * N + n];
        float f3 = g[(size_t)(k0 + 9) * N + n];
        uint32_t h01 = packh2(f0, f1);
        uint32_t h23 = packh2(f2, f3);
        *(uint2*)(dst + (size_t)blk * 256 + lane * 8) = make_uint2(h01, h23);
    }
}

__global__ __launch_bounds__(NTH_, 1)
void ensemble_mlp_mma(const float* __restrict__ states,
                      const float* __restrict__ actions,
                      const float* __restrict__ W0, const float* __restrict__ b0,
                      const float* __restrict__ W1, const float* __restrict__ b1,
                      const float* __restrict__ W2, const float* __restrict__ b2,
                      float* __restrict__ out)
{
    extern __shared__ char smc[];
    float* sb0 = (float*)(smc + SM_BI);
    float* sb1 = sb0 + 128;
    float* sb2 = sb1 + 128;

    const int tid  = threadIdx.x;
    const int wid  = tid >> 5;
    const int lane = tid & 31;
    const int qk   = lane & 3;     // k-quad within fragment
    const int rr   = lane >> 2;    // row (and B-col) within fragment
    const int j     = blockIdx.y;
    const int btile = blockIdx.x * TM_;
    const int rbase = wid * 16 + rr;

    // ---- stage weights (single fp16) + biases ----
    stage_w(W0 + (size_t)j * DIN_ * HID_, 2, 16, HID_, smc + SM_W0);  // k 0..31 (states)
    {   // actions part of W0 (k 32..39) as k8 fragments: single uint32 {h01}
        const float* g = W0 + (size_t)j * DIN_ * HID_;
        for (int idx = tid; idx < 16 * 32; idx += NTH_) {
            int lane2 = idx & 31;
            int nt = idx >> 5;
            int q = lane2 & 3, r2 = lane2 >> 2;
            int n = nt * 8 + r2;
            int k0 = 32 + q * 2;
            float f0 = g[(size_t)k0 * HID_ + n];
            float f1 = g[(size_t)(k0 + 1) * HID_ + n];
            *(uint32_t*)(smc + SM_W0A + (size_t)idx * 4) = packh2(f0, f1);
        }
    }
    stage_w(W1 + (size_t)j * HID_ * HID_, 8, 16, HID_, smc + SM_W1);
    stage_w(W2 + (size_t)j * HID_ * DS_,  8,  4, DS_,  smc + SM_W2);
    if (tid < HID_) { sb0[tid] = b0[j * HID_ + tid]; sb1[tid] = b1[j * HID_ + tid]; }
    if (tid < DS_)  { sb2[tid] = b2[j * DS_ + tid]; }
    __syncthreads();   // the ONLY barrier — i-loop below is barrier-free

    // per-lane fragment base pointers (inner offsets are compile-time constants)
    const char* w0b  = smc + SM_W0  + lane * 8;
    const char* w0ab = smc + SM_W0A + lane * 4;
    const char* w1b  = smc + SM_W1  + lane * 8;
    const char* w2b  = smc + SM_W2  + lane * 8;

    // per-thread gmem activation pointers (advance by one i-slice per iter)
    const float* srow = states  + ((size_t)btile + rbase) * DS_ + qk * 2;
    const float* arow = actions + ((size_t)btile + rbase) * DA_ + qk * 2;

    float sums[16], sqs[16];
    #pragma unroll
    for (int t = 0; t < 16; ++t) { sums[t] = 0.f; sqs[t] = 0.f; }

    uint32_t aH[32];

    for (int i = 0; i < E_; ++i) {
        // ================= layer 0: K=40 (2x k16 + 1x k8), N=128 =================
        {
            float acc[16][4];
            #pragma unroll
            for (int nt = 0; nt < 16; ++nt)
                #pragma unroll
                for (int t = 0; t < 4; ++t) acc[nt][t] = 0.f;

            // kc = 0,1 : states
            #pragma unroll
            for (int kc = 0; kc < 2; ++kc) {
                float2 x00 = __ldg((const float2*)(srow + kc * 16));
                float2 x01 = __ldg((const float2*)(srow + kc * 16 + 8 * DS_));
                float2 x10 = __ldg((const float2*)(srow + kc * 16 + 8));
                float2 x11 = __ldg((const float2*)(srow + kc * 16 + 8 + 8 * DS_));
                uint32_t ah[4];
                ah[0] = packh2(x00.x, x00.y);
                ah[1] = packh2(x01.x, x01.y);
                ah[2] = packh2(x10.x, x10.y);
                ah[3] = packh2(x11.x, x11.y);
                #pragma unroll
                for (int nt = 0; nt < 16; ++nt) {
                    uint2 bv = *(const uint2*)(w0b + (kc * 16 + nt) * 256);
                    mma16816(acc[nt], ah, bv.x, bv.y);
                }
            }
            // actions: k 32..39 as m16n8k8
            {
                float2 x00 = __ldg((const float2*)(arow));
                float2 x01 = __ldg((const float2*)(arow + 8 * DA_));
                uint32_t ah0 = packh2(x00.x, x00.y);
                uint32_t ah1 = packh2(x01.x, x01.y);
                #pragma unroll
                for (int nt = 0; nt < 16; ++nt) {
                    uint32_t bv = *(const uint32_t*)(w0ab + nt * 128);
                    mma1688(acc[nt], ah0, ah1, bv);
                }
            }
            #pragma unroll
            for (int nt = 0; nt < 16; ++nt) {
                float2 bb = *(const float2*)(sb0 + nt * 8 + qk * 2);
                cvt_act(acc[nt], bb, aH[2*nt], aH[2*nt+1]);
            }
        }

        // ================= layer 1: K=128, N=128 =================
        {
            float acc[16][4];
            #pragma unroll
            for (int nt = 0; nt < 16; ++nt)
                #pragma unroll
                for (int t = 0; t < 4; ++t) acc[nt][t] = 0.f;

            #pragma unroll
            for (int kc = 0; kc < 8; ++kc) {
                const uint32_t* ah = aH + 4 * kc;
                #pragma unroll
                for (int nt = 0; nt < 16; ++nt) {
                    uint2 bv = *(const uint2*)(w1b + (kc * 16 + nt) * 256);
                    mma16816(acc[nt], ah, bv.x, bv.y);
                }
            }
            #pragma unroll
            for (int nt = 0; nt < 16; ++nt) {
                float2 bb = *(const float2*)(sb1 + nt * 8 + qk * 2);
                cvt_act(acc[nt], bb, aH[2*nt], aH[2*nt+1]);
            }
        }

        // ================= layer 2: K=128, N=32; stats =================
        {
            float acc[4][4];
            #pragma unroll
            for (int nt = 0; nt < 4; ++nt)
                #pragma unroll
                for (int t = 0; t < 4; ++t) acc[nt][t] = 0.f;

            #pragma unroll
            for (int kc = 0; kc < 8; ++kc) {
                const uint32_t* ah = aH + 4 * kc;
                #pragma unroll
                for (int nt = 0; nt < 4; ++nt) {
                    uint2 bv = *(const uint2*)(w2b + (kc * 4 + nt) * 256);
                    mma16816(acc[nt], ah, bv.x, bv.y);
                }
            }
            #pragma unroll
            for (int nt = 0; nt < 4; ++nt) {
                float2 bb = *(const float2*)(sb2 + nt * 8 + qk * 2);
                float p0 = acc[nt][0] + bb.x;
                float p1 = acc[nt][1] + bb.y;
                float p2 = acc[nt][2] + bb.x;
                float p3 = acc[nt][3] + bb.y;
                sums[nt*4+0] += p0; sqs[nt*4+0] = fmaf(p0, p0, sqs[nt*4+0]);
                sums[nt*4+1] += p1; sqs[nt*4+1] = fmaf(p1, p1, sqs[nt*4+1]);
                sums[nt*4+2] += p2; sqs[nt*4+2] = fmaf(p2, p2, sqs[nt*4+2]);
                sums[nt*4+3] += p3; sqs[nt*4+3] = fmaf(p3, p3, sqs[nt*4+3]);
            }
        }

        srow += (size_t)B_ * DS_;
        arow += (size_t)B_ * DA_;
    }

    // ---- epilogue: mean/var over the 8 members; outputs ----
    const size_t var_off = (size_t)E_ * B_ * DS_;
    const size_t row_lo = (size_t)j * B_ + btile + rbase;
    const size_t row_hi = row_lo + 8;
    #pragma unroll
    for (int nt = 0; nt < 4; ++nt) {
        const int c0 = nt * 8 + qk * 2;
        {
            const size_t o = row_lo * DS_ + c0;
            float2 st = __ldg((const float2*)(states + o));
            float m0 = sums[nt*4+0] * 0.125f;
            float m1 = sums[nt*4+1] * 0.125f;
            float v0 = (sqs[nt*4+0] - 8.f * m0 * m0) * (1.f / 7.f);
            float v1 = (sqs[nt*4+1] - 8.f * m1 * m1) * (1.f / 7.f);
            *(float2*)(out + o)           = make_float2(m0 + st.x, m1 + st.y);
            *(float2*)(out + var_off + o) = make_float2(v0, v1);
        }
        {
            const size_t o = row_hi * DS_ + c0;
            float2 st = __ldg((const float2*)(states + o));
            float m2 = sums[nt*4+2] * 0.125f;
            float m3 = sums[nt*4+3] * 0.125f;
            float v2 = (sqs[nt*4+2] - 8.f * m2 * m2) * (1.f / 7.f);
            float v3 = (sqs[nt*4+3] - 8.f * m3 * m3) * (1.f / 7.f);
            *(float2*)(out + o)           = make_float2(m2 + st.x, m3 + st.y);
            *(float2*)(out + var_off + o) = make_float2(v2, v3);
        }
    }
}

extern "C" void kernel_launch(void* const* d_in, const int* in_sizes, int n_in,
                              void* d_out, int out_size)
{
    const float* states  = (const float*)d_in[0];
    const float* actions = (const float*)d_in[1];
    const float* W0      = (const float*)d_in[2];
    const float* b0      = (const float*)d_in[3];
    const float* W1      = (const float*)d_in[4];
    const float* b1      = (const float*)d_in[5];
    const float* W2      = (const float*)d_in[6];
    const float* b2      = (const float*)d_in[7];
    float* out = (float*)d_out;

    cudaFuncSetAttribute(ensemble_mlp_mma,
                         cudaFuncAttributeMaxDynamicSharedMemorySize, SM_TOTAL);

    dim3 grid(B_ / TM_, E_);   // 128 x 8 = 1024 CTAs
    ensemble_mlp_mma<<<grid, NTH_, SM_TOTAL>>>(states, actions,
                                               W0, b0, W1, b1, W2, b2, out);
}